// round 5
// baseline (speedup 1.0000x reference)
#include <cuda_runtime.h>
#include <math.h>

#define Bq 2
#define Nv 4
#define Cc 128
#define NH 8
#define HDx 16
#define Pp 4
#define Hh 96
#define Ww 96
#define HW 9216
#define ROWS 147456   // Bq*NH*HW
#define CHW (Cc*HW)   // 1179648

// ---------------- scratch (device globals; no allocation allowed) ----------
__device__ float g_q[Bq*CHW];        // q in net layout
__device__ float g_vt[Bq*Nv*CHW];    // v in net layout (hd contiguous)
__device__ float g_dw[Bq*CHW];       // depthwise+gelu out (std layout)
__device__ float g_net[ROWS*HDx];    // GRU hidden state
__device__ float g_off[ROWS*Pp*2];   // current offsets
__device__ float g_attn[ROWS*Nv*Pp]; // attn logits -> softmaxed weights
__device__ float g_entrow[ROWS];
__device__ float g_agg[Bq*CHW];      // aggregated samples (pixel-major)
__device__ float g_tmp[Bq*CHW];      // o1 output (std layout)
__device__ float g_tbias[Bq*NH*Nv];
__device__ int   g_near[Bq];

__device__ __forceinline__ float geluf(float x){ return 0.5f*x*(1.f+erff(x*0.70710678118f)); }
__device__ __forceinline__ float sigmf(float x){ return 1.f/(1.f+expf(-x)); }
__device__ __forceinline__ float clamp1(float x){ return fminf(1.f,fmaxf(-1.f,x)); }

// ---------------- small prep: nearest_idx + time bias ----------------------
__global__ void k_prep(const float* __restrict__ rel, const float* __restrict__ tenc,
                       const float* __restrict__ tw, const float* __restrict__ tb){
    int t = threadIdx.x;
    if(t < Bq){
        float best = fabsf(rel[t*Nv]); int bi = 0;
        for(int n=1;n<Nv;n++){ float v = fabsf(rel[t*Nv+n]); if(v<best){best=v;bi=n;} }
        g_near[t] = bi;
    }
    if(t < Bq*NH*Nv){
        int b = t>>5; int h = (t>>2)&7; int n = t&3;
        float s = tb[h];
        for(int k=0;k<64;k++) s += tenc[(b*Nv+n)*64+k]*tw[h*64+k];
        g_tbias[(b*NH+h)*Nv+n] = s;
    }
}

// ---------------- generic conv1x1 (128x128 GEMM per image) -----------------
// IN_T: 0 = (C,HW) std, 1 = (HW,C) pixel-major
// OUT_T: 0 = (C,HW) std, 1 = net layout [(img*8+head)*HW+pix]*16+hd
// ACT: 0 none, 1 gelu, 2 gate (val * sigmoid(gate[o]))
template<int IN_T, int OUT_T, int ACT>
__global__ __launch_bounds__(256) void k_conv(const float* __restrict__ in,
                                              const float* __restrict__ w,
                                              const float* __restrict__ bias,
                                              float* __restrict__ out,
                                              const float* __restrict__ gate){
    __shared__ float in_s[32][68];
    __shared__ float w_s[32][132];
    int img  = blockIdx.y;
    int pix0 = blockIdx.x*64;
    int t    = threadIdx.x;
    int oq   = t & 31;   // o-quad: o = oq*4..oq*4+3
    int pg   = t >> 5;   // pixel group: p = pg*8..pg*8+7
    const float* inb = in + (long)img*CHW;

    float acc[4][8];
    #pragma unroll
    for(int k=0;k<4;k++)
        #pragma unroll
        for(int j=0;j<8;j++) acc[k][j]=0.f;

    for(int c0=0;c0<Cc;c0+=32){
        #pragma unroll
        for(int l=0;l<8;l++){
            int lin = l*256+t;
            if(IN_T==0){ int ci=lin>>6, p=lin&63; in_s[ci][p] = inb[(c0+ci)*HW + pix0+p]; }
            else       { int p=lin>>5, ci=lin&31; in_s[ci][p] = inb[(long)(pix0+p)*Cc + c0+ci]; }
        }
        #pragma unroll
        for(int l=0;l<16;l++){
            int lin = l*256+t; int ci=lin&31, o=lin>>5;
            w_s[ci][o] = w[o*Cc + c0+ci];
        }
        __syncthreads();
        #pragma unroll
        for(int ci=0;ci<32;ci++){
            float4 wv = *(const float4*)&w_s[ci][oq*4];
            float4 xa = *(const float4*)&in_s[ci][pg*8];
            float4 xb = *(const float4*)&in_s[ci][pg*8+4];
            float ws[4] = {wv.x,wv.y,wv.z,wv.w};
            float xs[8] = {xa.x,xa.y,xa.z,xa.w,xb.x,xb.y,xb.z,xb.w};
            #pragma unroll
            for(int k=0;k<4;k++)
                #pragma unroll
                for(int j=0;j<8;j++) acc[k][j] += ws[k]*xs[j];
        }
        __syncthreads();
    }

    int o0 = oq*4;
    float bv[4], gv[4];
    #pragma unroll
    for(int k=0;k<4;k++){
        bv[k] = bias[o0+k];
        if(ACT==2) gv[k] = sigmf(gate[o0+k]); else gv[k]=1.f;
    }
    if(OUT_T==0){
        #pragma unroll
        for(int k=0;k<4;k++){
            float* op = out + (long)img*CHW + (o0+k)*HW + pix0 + pg*8;
            #pragma unroll
            for(int j=0;j<8;j++){
                float v = acc[k][j] + bv[k];
                if(ACT==1) v = geluf(v);
                if(ACT==2) v *= gv[k];
                op[j] = v;
            }
        }
    } else {
        int grp = o0>>4, olo = o0&15;
        float* ob = out + (long)img*CHW + (long)grp*HW*16 + olo;
        #pragma unroll
        for(int j=0;j<8;j++){
            int p = pix0 + pg*8 + j;
            float4 v;
            v.x = acc[0][j]+bv[0]; v.y = acc[1][j]+bv[1];
            v.z = acc[2][j]+bv[2]; v.w = acc[3][j]+bv[3];
            *(float4*)(ob + (long)p*16) = v;
        }
    }
}

// ---------------- depthwise 7x7 + bias + exact gelu ------------------------
__global__ __launch_bounds__(256) void k_dw(const float* __restrict__ q,
                                            const float* __restrict__ w,
                                            const float* __restrict__ b,
                                            float* __restrict__ out){
    __shared__ float pl[9216];
    __shared__ float wf[49];
    int plane = blockIdx.x;        // b*C + c
    int c = plane & 127;
    int t = threadIdx.x;
    #pragma unroll
    for(int l=0;l<36;l++) pl[l*256+t] = q[(long)plane*HW + l*256+t];
    if(t<49) wf[t] = w[c*49+t];
    __syncthreads();
    float bc = b[c];
    for(int g=t; g<1152; g+=256){
        int y = g/12, x0 = (g%12)*8;
        float acc[8];
        #pragma unroll
        for(int j=0;j<8;j++) acc[j]=0.f;
        #pragma unroll
        for(int ky=0;ky<7;ky++){
            int yy = y+ky-3;
            if(yy<0 || yy>=96) continue;
            float rowv[14];
            #pragma unroll
            for(int i=0;i<14;i++){
                int xx = x0-3+i;
                rowv[i] = (xx>=0 && xx<96) ? pl[yy*96+xx] : 0.f;
            }
            #pragma unroll
            for(int kx=0;kx<7;kx++){
                float wv = wf[ky*7+kx];
                #pragma unroll
                for(int j=0;j<8;j++) acc[j] += rowv[kx+j]*wv;
            }
        }
        #pragma unroll
        for(int j=0;j<8;j++){
            out[(long)plane*HW + y*96 + x0 + j] = geluf(acc[j]+bc);
        }
    }
}

// ---------------- correlation argmax -> init offsets, zero attn ------------
__global__ __launch_bounds__(256) void k_corr(){
    int row = blockIdx.x*256 + threadIdx.x;
    int b = row/(NH*HW); int r1 = row%(NH*HW);
    int head = r1/HW; int pix = r1%HW;
    int y = pix/Ww, x = pix%Ww;
    const float4* qp = (const float4*)(g_q + (long)row*16);
    float4 q0=qp[0], q1=qp[1], q2=qp[2], q3=qp[3];
    int nidx = g_near[b];
    const float* vb = g_vt + (((long)(b*Nv+nidx)*NH + head)*HW)*16;
    const int SDX[5] = {0,-1,1,0,0};
    const int SDY[5] = {0,0,0,-1,1};
    float best = -1e30f; int bi = 0;
    #pragma unroll
    for(int k=0;k<5;k++){
        int yy = y - SDY[k], xx = x - SDX[k];
        float s = 0.f;
        if(yy>=0 && yy<Hh && xx>=0 && xx<Ww){
            const float4* vp = (const float4*)(vb + (long)(yy*Ww+xx)*16);
            float4 v0=vp[0], v1=vp[1], v2=vp[2], v3=vp[3];
            s = q0.x*v0.x+q0.y*v0.y+q0.z*v0.z+q0.w*v0.w
              + q1.x*v1.x+q1.y*v1.y+q1.z*v1.z+q1.w*v1.w
              + q2.x*v2.x+q2.y*v2.y+q2.z*v2.z+q2.w*v2.w
              + q3.x*v3.x+q3.y*v3.y+q3.z*v3.z+q3.w*v3.w;
        }
        if(s > best){ best = s; bi = k; }   // first-max semantics
    }
    // comp0 (x) = dy*2/W ; comp1 (y) = dx*2/H  (replicating reference's crossed stack)
    float offx = SDY[bi]*(2.f/96.f);
    float offy = SDX[bi]*(2.f/96.f);
    float* op = g_off + (long)row*8;
    #pragma unroll
    for(int p=0;p<4;p++){ op[p*2]=offx; op[p*2+1]=offy; }
    float4 z4 = make_float4(0.f,0.f,0.f,0.f);
    float4* ap = (float4*)(g_attn + (long)row*16);
    ap[0]=z4; ap[1]=z4; ap[2]=z4; ap[3]=z4;
}

// ---------------- bilinear helper ------------------------------------------
struct BL { int i00,i10,i01,i11; float w00,w10,w01,w11; };
__device__ __forceinline__ BL mk_bl(float gx, float gy){
    float ix = (gx+1.f)*47.5f;
    float iy = (gy+1.f)*47.5f;
    float fx = floorf(ix), fy = floorf(iy);
    float wx = ix-fx, wy = iy-fy;
    int x0 = max(0,min(95,(int)fx)); int x1 = min(95,x0+1);
    int y0 = max(0,min(95,(int)fy)); int y1 = min(95,y0+1);
    BL r;
    r.i00=(y0*96+x0)*16; r.i10=(y0*96+x1)*16;
    r.i01=(y1*96+x0)*16; r.i11=(y1*96+x1)*16;
    r.w00=(1.f-wx)*(1.f-wy); r.w10=wx*(1.f-wy);
    r.w01=(1.f-wx)*wy;       r.w11=wx*wy;
    return r;
}

// ---------------- fused GRU iteration --------------------------------------
__global__ __launch_bounds__(128) void k_gru(const float* __restrict__ wih, const float* __restrict__ whh,
                                             const float* __restrict__ bih, const float* __restrict__ bhh,
                                             const float* __restrict__ offw, const float* __restrict__ offb,
                                             const float* __restrict__ aw, const float* __restrict__ ab){
    __shared__ float s_wih[48*18], s_whh[48*16], s_bih[48], s_bhh[48];
    __shared__ float s_offw[128], s_offb[8], s_aw[64], s_ab[4];
    int t = threadIdx.x;
    for(int i=t;i<864;i+=128) s_wih[i]=wih[i];
    for(int i=t;i<768;i+=128) s_whh[i]=whh[i];
    if(t<48){ s_bih[t]=bih[t]; s_bhh[t]=bhh[t]; }
    if(t<128) s_offw[t]=offw[t];
    if(t<8)  s_offb[t]=offb[t];
    if(t<64) s_aw[t]=aw[t];
    if(t<4)  s_ab[t]=ab[t];
    __syncthreads();

    int row = blockIdx.x*128 + t;
    int b = row/(NH*HW); int r1 = row%(NH*HW);
    int head = r1/HW; int pix = r1%HW;
    int y = pix/Ww, x = pix%Ww;
    float* offp = g_off + (long)row*8;
    float ox = offp[0], oy = offp[1];
    float gx = clamp1(x*(2.f/95.f)-1.f + ox);
    float gy = clamp1(y*(2.f/95.f)-1.f + oy);

    // sample v_nearest (16 ch)
    int nidx = g_near[b];
    const float* vb = g_vt + (((long)(b*Nv+nidx)*NH + head)*HW)*16;
    BL bl = mk_bl(gx, gy);
    float s[16];
    {
        const float4* p00 = (const float4*)(vb + bl.i00);
        const float4* p10 = (const float4*)(vb + bl.i10);
        const float4* p01 = (const float4*)(vb + bl.i01);
        const float4* p11 = (const float4*)(vb + bl.i11);
        #pragma unroll
        for(int g=0; g<4; g++){
            float4 a=p00[g], c=p10[g], d=p01[g], e=p11[g];
            s[g*4+0]=bl.w00*a.x+bl.w10*c.x+bl.w01*d.x+bl.w11*e.x;
            s[g*4+1]=bl.w00*a.y+bl.w10*c.y+bl.w01*d.y+bl.w11*e.y;
            s[g*4+2]=bl.w00*a.z+bl.w10*c.z+bl.w01*d.z+bl.w11*e.z;
            s[g*4+3]=bl.w00*a.w+bl.w10*c.w+bl.w01*d.w+bl.w11*e.w;
        }
    }
    float h_[16];
    {
        float4* np = (float4*)(g_net + (long)row*16);
        #pragma unroll
        for(int g=0; g<4; g++){
            float4 v = np[g];
            h_[g*4+0]=v.x; h_[g*4+1]=v.y; h_[g*4+2]=v.z; h_[g*4+3]=v.w;
        }
    }
    float r[16];
    #pragma unroll
    for(int k=0;k<16;k++){
        float sum = s_bih[k] + s_bhh[k];
        #pragma unroll
        for(int j=0;j<16;j++) sum += s_wih[k*18+j]*s[j];
        sum += s_wih[k*18+16]*ox + s_wih[k*18+17]*oy;
        #pragma unroll
        for(int j=0;j<16;j++) sum += s_whh[k*16+j]*h_[j];
        r[k] = sigmf(sum);
    }
    float nn[16];
    #pragma unroll
    for(int k=0;k<16;k++){
        int kk = 32+k;
        float gin = s_bih[kk];
        #pragma unroll
        for(int j=0;j<16;j++) gin += s_wih[kk*18+j]*s[j];
        gin += s_wih[kk*18+16]*ox + s_wih[kk*18+17]*oy;
        float ghn = s_bhh[kk];
        #pragma unroll
        for(int j=0;j<16;j++) ghn += s_whh[kk*16+j]*h_[j];
        nn[k] = tanhf(gin + r[k]*ghn);
    }
    float nh[16];
    #pragma unroll
    for(int k=0;k<16;k++){
        int kk = 16+k;
        float zs = s_bih[kk] + s_bhh[kk];
        #pragma unroll
        for(int j=0;j<16;j++) zs += s_wih[kk*18+j]*s[j];
        zs += s_wih[kk*18+16]*ox + s_wih[kk*18+17]*oy;
        #pragma unroll
        for(int j=0;j<16;j++) zs += s_whh[kk*16+j]*h_[j];
        float z = sigmf(zs);
        nh[k] = (1.f-z)*nn[k] + z*h_[k];
    }
    {
        float4* np = (float4*)(g_net + (long)row*16);
        #pragma unroll
        for(int g=0; g<4; g++)
            np[g] = make_float4(nh[g*4+0], nh[g*4+1], nh[g*4+2], nh[g*4+3]);
    }
    // d_off
    #pragma unroll
    for(int i=0;i<8;i++){
        float d = s_offb[i];
        #pragma unroll
        for(int k=0;k<16;k++) d += s_offw[i*16+k]*nh[k];
        if(i==0) offp[0] = ox + d;
        else if(i==1) offp[1] = oy + d;
        else offp[i] = offp[i] + d;
    }
    // d_attn (broadcast over n)
    float* ap = g_attn + (long)row*16;
    #pragma unroll
    for(int p=0;p<4;p++){
        float d = s_ab[p];
        #pragma unroll
        for(int k=0;k<16;k++) d += s_aw[p*16+k]*nh[k];
        #pragma unroll
        for(int n=0;n<4;n++) ap[n*4+p] += d;
    }
}

// ---------------- softmax over N*P + entropy per row -----------------------
__global__ __launch_bounds__(256) void k_soft(){
    int row = blockIdx.x*256 + threadIdx.x;
    int b = row/(NH*HW); int head = (row/HW)%NH;
    float* ap = g_attn + (long)row*16;
    float a[16];
    #pragma unroll
    for(int i=0;i<16;i++) a[i] = ap[i];
    #pragma unroll
    for(int n=0;n<4;n++){
        float tb = g_tbias[(b*NH+head)*Nv + n];
        #pragma unroll
        for(int p=0;p<4;p++) a[n*4+p] += tb;
    }
    float m = a[0];
    #pragma unroll
    for(int i=1;i<16;i++) m = fmaxf(m, a[i]);
    float sum = 0.f;
    #pragma unroll
    for(int i=0;i<16;i++){ a[i] = expf(a[i]-m); sum += a[i]; }
    float inv = 1.f/sum;
    float ent = 0.f;
    #pragma unroll
    for(int i=0;i<16;i++){
        float w = a[i]*inv;
        ap[i] = w;
        ent -= w*logf(w + 1e-8f);
    }
    g_entrow[row] = ent;
}

// ---------------- final deformable sampling + aggregation ------------------
__global__ __launch_bounds__(128) void k_final(){
    int row = blockIdx.x*128 + threadIdx.x;
    int b = row/(NH*HW); int r1 = row%(NH*HW);
    int head = r1/HW; int pix = r1%HW;
    int y = pix/Ww, x = pix%Ww;
    float a[16];
    {
        float* ap = g_attn + (long)row*16;
        #pragma unroll
        for(int i=0;i<16;i++) a[i] = ap[i];
    }
    float off[8];
    {
        float* op = g_off + (long)row*8;
        #pragma unroll
        for(int i=0;i<8;i++) off[i] = op[i];
    }
    float bx = x*(2.f/95.f)-1.f, by = y*(2.f/95.f)-1.f;
    float4 acc[4];
    #pragma unroll
    for(int g=0;g<4;g++) acc[g] = make_float4(0.f,0.f,0.f,0.f);

    #pragma unroll
    for(int p=0;p<4;p++){
        float gx = clamp1(bx + off[2*p]);
        float gy = clamp1(by + off[2*p+1]);
        BL bl = mk_bl(gx, gy);
        #pragma unroll
        for(int n=0;n<4;n++){
            float anp = a[n*4+p];
            const float* vb = g_vt + (((long)(b*Nv+n)*NH + head)*HW)*16;
            float c00 = anp*bl.w00, c10 = anp*bl.w10, c01 = anp*bl.w01, c11 = anp*bl.w11;
            const float4* p00 = (const float4*)(vb + bl.i00);
            const float4* p10 = (const float4*)(vb + bl.i10);
            const float4* p01 = (const float4*)(vb + bl.i01);
            const float4* p11 = (const float4*)(vb + bl.i11);
            #pragma unroll
            for(int g=0;g<4;g++){
                float4 v0=p00[g], v1=p10[g], v2=p01[g], v3=p11[g];
                acc[g].x += c00*v0.x + c10*v1.x + c01*v2.x + c11*v3.x;
                acc[g].y += c00*v0.y + c10*v1.y + c01*v2.y + c11*v3.y;
                acc[g].z += c00*v0.z + c10*v1.z + c01*v2.z + c11*v3.z;
                acc[g].w += c00*v0.w + c10*v1.w + c01*v2.w + c11*v3.w;
            }
        }
    }
    // pixel-major aggregate: g_agg[(b*HW+pix)*128 + head*16 + hd]
    float4* og = (float4*)(g_agg + ((long)b*HW + pix)*Cc + head*16);
    #pragma unroll
    for(int g=0;g<4;g++) og[g] = acc[g];
}

// ---------------- entropy mean over heads -> confidence + entropy ----------
__global__ __launch_bounds__(256) void k_ent(float* __restrict__ outp){
    int i = blockIdx.x*256 + threadIdx.x;    // Bq*HW = 18432
    int b = i/HW, pix = i%HW;
    float e = 0.f;
    #pragma unroll
    for(int h=0;h<8;h++) e += g_entrow[(long)(b*NH+h)*HW + pix];
    e *= 0.125f;
    float conf = 1.f - fminf(1.f, fmaxf(0.f, e/(2.77258872f + 1e-8f)));
    outp[(long)Bq*CHW + i]          = conf;
    outp[(long)Bq*CHW + Bq*HW + i]  = e;
}

// ---------------- launch ---------------------------------------------------
extern "C" void kernel_launch(void* const* d_in, const int* in_sizes, int n_in,
                              void* d_out, int out_size){
    const float* query = (const float*)d_in[0];
    const float* values= (const float*)d_in[1];
    const float* rel   = (const float*)d_in[2];
    const float* tenc  = (const float*)d_in[3];
    const float* qw    = (const float*)d_in[4];
    const float* qb    = (const float*)d_in[5];
    const float* vw    = (const float*)d_in[6];
    const float* vb    = (const float*)d_in[7];
    const float* dww   = (const float*)d_in[8];
    const float* dwb   = (const float*)d_in[9];
    const float* pww   = (const float*)d_in[10];
    const float* pwb   = (const float*)d_in[11];
    const float* wih   = (const float*)d_in[12];
    const float* whh   = (const float*)d_in[13];
    const float* bih   = (const float*)d_in[14];
    const float* bhh   = (const float*)d_in[15];
    const float* offw  = (const float*)d_in[16];
    const float* offb  = (const float*)d_in[17];
    const float* aw    = (const float*)d_in[18];
    const float* ab    = (const float*)d_in[19];
    const float* tw    = (const float*)d_in[20];
    const float* tb    = (const float*)d_in[21];
    const float* o1w   = (const float*)d_in[22];
    const float* o1b   = (const float*)d_in[23];
    const float* o2w   = (const float*)d_in[24];
    const float* o2b   = (const float*)d_in[25];
    const float* gate  = (const float*)d_in[26];
    float* outp = (float*)d_out;

    float *p_q, *p_vt, *p_dw, *p_net, *p_agg, *p_tmp;
    cudaGetSymbolAddress((void**)&p_q,   g_q);
    cudaGetSymbolAddress((void**)&p_vt,  g_vt);
    cudaGetSymbolAddress((void**)&p_dw,  g_dw);
    cudaGetSymbolAddress((void**)&p_net, g_net);
    cudaGetSymbolAddress((void**)&p_agg, g_agg);
    cudaGetSymbolAddress((void**)&p_tmp, g_tmp);

    k_prep<<<1,64>>>(rel, tenc, tw, tb);
    k_conv<0,1,0><<<dim3(144,Bq),    256>>>(query,  qw,  qb,  p_q,   nullptr); // q -> net layout
    k_conv<0,1,0><<<dim3(144,Bq*Nv), 256>>>(values, vw,  vb,  p_vt,  nullptr); // v -> net layout
    k_dw  <<<Bq*Cc, 256>>>(query, dww, dwb, p_dw);                              // depthwise + gelu
    k_conv<0,1,0><<<dim3(144,Bq),    256>>>(p_dw,   pww, pwb, p_net, nullptr); // pw -> net (GRU h0)
    k_corr<<<ROWS/256, 256>>>();
    for(int it=0; it<3; it++)
        k_gru<<<ROWS/128, 128>>>(wih, whh, bih, bhh, offw, offb, aw, ab);
    k_soft <<<ROWS/256, 256>>>();
    k_final<<<ROWS/128, 128>>>();
    k_conv<1,0,1><<<dim3(144,Bq), 256>>>(p_agg, o1w, o1b, p_tmp, nullptr);     // o1 + gelu
    k_conv<0,0,2><<<dim3(144,Bq), 256>>>(p_tmp, o2w, o2b, outp,  gate);        // o2 * sigmoid(gate)
    k_ent<<<Bq*HW/256, 256>>>(outp);
}

// round 12
// speedup vs baseline: 1.0777x; 1.0777x over previous
#include <cuda_runtime.h>
#include <math.h>

#define Bq 2
#define Nv 4
#define Cc 128
#define NH 8
#define HDx 16
#define Pp 4
#define Hh 96
#define Ww 96
#define HW 9216
#define ROWS 147456   // Bq*NH*HW
#define CHW (Cc*HW)   // 1179648

// ---------------- scratch (device globals; no allocation allowed) ----------
__device__ float g_q[Bq*CHW];        // q in net layout
__device__ float g_vt[Bq*Nv*CHW];    // v in net layout (hd contiguous)
__device__ float g_dw[Bq*CHW];       // depthwise+gelu out (std layout)
__device__ float g_net[ROWS*HDx];    // GRU hidden state
__device__ float g_off[ROWS*Pp*2];   // current offsets
__device__ float g_attn[ROWS*Nv*Pp]; // attn logits
__device__ float g_entrow[ROWS];
__device__ float g_agg[Bq*CHW];      // aggregated samples (pixel-major)
__device__ float g_tmp[Bq*CHW];      // o1 output (std layout)
__device__ float g_tbias[Bq*NH*Nv];
__device__ int   g_near[Bq];

__device__ __forceinline__ float geluf(float x){ return 0.5f*x*(1.f+erff(x*0.70710678118f)); }
__device__ __forceinline__ float sigmf(float x){ return 1.f/(1.f+expf(-x)); }
__device__ __forceinline__ float clamp1(float x){ return fminf(1.f,fmaxf(-1.f,x)); }

// ---------------- small prep: nearest_idx + time bias ----------------------
__global__ void k_prep(const float* __restrict__ rel, const float* __restrict__ tenc,
                       const float* __restrict__ tw, const float* __restrict__ tb){
    int t = threadIdx.x;
    if(t < Bq){
        float best = fabsf(rel[t*Nv]); int bi = 0;
        for(int n=1;n<Nv;n++){ float v = fabsf(rel[t*Nv+n]); if(v<best){best=v;bi=n;} }
        g_near[t] = bi;
    }
    if(t < Bq*NH*Nv){
        int b = t>>5; int h = (t>>2)&7; int n = t&3;
        float s = tb[h];
        for(int k=0;k<64;k++) s += tenc[(b*Nv+n)*64+k]*tw[h*64+k];
        g_tbias[(b*NH+h)*Nv+n] = s;
    }
}

// ---------------- generic conv1x1 (128x128 GEMM per image) -----------------
// IN_T: 0 = (C,HW) std, 1 = (HW,C) pixel-major
// OUT_T: 0 = (C,HW) std, 1 = net layout [(img*8+head)*HW+pix]*16+hd
// ACT: 0 none, 1 gelu, 2 gate (val * sigmoid(gate[o]))
template<int IN_T, int OUT_T, int ACT>
__global__ __launch_bounds__(256) void k_conv(const float* __restrict__ in,
                                              const float* __restrict__ w,
                                              const float* __restrict__ bias,
                                              float* __restrict__ out,
                                              const float* __restrict__ gate){
    __shared__ float in_s[32][68];
    __shared__ float w_s[32][132];
    int img  = blockIdx.y;
    int pix0 = blockIdx.x*64;
    int t    = threadIdx.x;
    int oq   = t & 31;   // o-quad: o = oq*4..oq*4+3
    int pg   = t >> 5;   // pixel group: p = pg*8..pg*8+7
    const float* inb = in + (long)img*CHW;

    float acc[4][8];
    #pragma unroll
    for(int k=0;k<4;k++)
        #pragma unroll
        for(int j=0;j<8;j++) acc[k][j]=0.f;

    for(int c0=0;c0<Cc;c0+=32){
        #pragma unroll
        for(int l=0;l<8;l++){
            int lin = l*256+t;
            if(IN_T==0){ int ci=lin>>6, p=lin&63; in_s[ci][p] = inb[(c0+ci)*HW + pix0+p]; }
            else       { int p=lin>>5, ci=lin&31; in_s[ci][p] = inb[(long)(pix0+p)*Cc + c0+ci]; }
        }
        #pragma unroll
        for(int l=0;l<16;l++){
            int lin = l*256+t; int ci=lin&31, o=lin>>5;
            w_s[ci][o] = w[o*Cc + c0+ci];
        }
        __syncthreads();
        #pragma unroll
        for(int ci=0;ci<32;ci++){
            float4 wv = *(const float4*)&w_s[ci][oq*4];
            float4 xa = *(const float4*)&in_s[ci][pg*8];
            float4 xb = *(const float4*)&in_s[ci][pg*8+4];
            float ws[4] = {wv.x,wv.y,wv.z,wv.w};
            float xs[8] = {xa.x,xa.y,xa.z,xa.w,xb.x,xb.y,xb.z,xb.w};
            #pragma unroll
            for(int k=0;k<4;k++)
                #pragma unroll
                for(int j=0;j<8;j++) acc[k][j] += ws[k]*xs[j];
        }
        __syncthreads();
    }

    int o0 = oq*4;
    float bv[4], gv[4];
    #pragma unroll
    for(int k=0;k<4;k++){
        bv[k] = bias[o0+k];
        if(ACT==2) gv[k] = sigmf(gate[o0+k]); else gv[k]=1.f;
    }
    if(OUT_T==0){
        #pragma unroll
        for(int k=0;k<4;k++){
            float* op = out + (long)img*CHW + (o0+k)*HW + pix0 + pg*8;
            #pragma unroll
            for(int j=0;j<8;j++){
                float v = acc[k][j] + bv[k];
                if(ACT==1) v = geluf(v);
                if(ACT==2) v *= gv[k];
                op[j] = v;
            }
        }
    } else {
        int grp = o0>>4, olo = o0&15;
        float* ob = out + (long)img*CHW + (long)grp*HW*16 + olo;
        #pragma unroll
        for(int j=0;j<8;j++){
            int p = pix0 + pg*8 + j;
            float4 v;
            v.x = acc[0][j]+bv[0]; v.y = acc[1][j]+bv[1];
            v.z = acc[2][j]+bv[2]; v.w = acc[3][j]+bv[3];
            *(float4*)(ob + (long)p*16) = v;
        }
    }
}

// ---------------- depthwise 7x7 + bias + exact gelu (R5 scalar, proven) ----
__global__ __launch_bounds__(256) void k_dw(const float* __restrict__ q,
                                            const float* __restrict__ w,
                                            const float* __restrict__ b,
                                            float* __restrict__ out){
    __shared__ float pl[9216];
    __shared__ float wf[49];
    int plane = blockIdx.x;        // b*C + c
    int c = plane & 127;
    int t = threadIdx.x;
    #pragma unroll
    for(int l=0;l<36;l++) pl[l*256+t] = q[(long)plane*HW + l*256+t];
    if(t<49) wf[t] = w[c*49+t];
    __syncthreads();
    float bc = b[c];
    for(int g=t; g<1152; g+=256){
        int y = g/12, x0 = (g%12)*8;
        float acc[8];
        #pragma unroll
        for(int j=0;j<8;j++) acc[j]=0.f;
        #pragma unroll
        for(int ky=0;ky<7;ky++){
            int yy = y+ky-3;
            if(yy<0 || yy>=96) continue;
            float rowv[14];
            #pragma unroll
            for(int i=0;i<14;i++){
                int xx = x0-3+i;
                rowv[i] = (xx>=0 && xx<96) ? pl[yy*96+xx] : 0.f;
            }
            #pragma unroll
            for(int kx=0;kx<7;kx++){
                float wv = wf[ky*7+kx];
                #pragma unroll
                for(int j=0;j<8;j++) acc[j] += rowv[kx+j]*wv;
            }
        }
        #pragma unroll
        for(int j=0;j<8;j++){
            out[(long)plane*HW + y*96 + x0 + j] = geluf(acc[j]+bc);
        }
    }
}

// ---------------- correlation argmax -> init offsets, zero attn ------------
__global__ __launch_bounds__(256) void k_corr(){
    int row = blockIdx.x*256 + threadIdx.x;
    int b = row/(NH*HW); int r1 = row%(NH*HW);
    int head = r1/HW; int pix = r1%HW;
    int y = pix/Ww, x = pix%Ww;
    const float4* qp = (const float4*)(g_q + (long)row*16);
    float4 q0=qp[0], q1=qp[1], q2=qp[2], q3=qp[3];
    int nidx = g_near[b];
    const float* vb = g_vt + (((long)(b*Nv+nidx)*NH + head)*HW)*16;
    const int SDX[5] = {0,-1,1,0,0};
    const int SDY[5] = {0,0,0,-1,1};
    float best = -1e30f; int bi = 0;
    #pragma unroll
    for(int k=0;k<5;k++){
        int yy = y - SDY[k], xx = x - SDX[k];
        float s = 0.f;
        if(yy>=0 && yy<Hh && xx>=0 && xx<Ww){
            const float4* vp = (const float4*)(vb + (long)(yy*Ww+xx)*16);
            float4 v0=vp[0], v1=vp[1], v2=vp[2], v3=vp[3];
            s = q0.x*v0.x+q0.y*v0.y+q0.z*v0.z+q0.w*v0.w
              + q1.x*v1.x+q1.y*v1.y+q1.z*v1.z+q1.w*v1.w
              + q2.x*v2.x+q2.y*v2.y+q2.z*v2.z+q2.w*v2.w
              + q3.x*v3.x+q3.y*v3.y+q3.z*v3.z+q3.w*v3.w;
        }
        if(s > best){ best = s; bi = k; }   // first-max semantics
    }
    float offx = SDY[bi]*(2.f/96.f);
    float offy = SDX[bi]*(2.f/96.f);
    float* op = g_off + (long)row*8;
    #pragma unroll
    for(int p=0;p<4;p++){ op[p*2]=offx; op[p*2+1]=offy; }
    float4 z4 = make_float4(0.f,0.f,0.f,0.f);
    float4* ap = (float4*)(g_attn + (long)row*16);
    ap[0]=z4; ap[1]=z4; ap[2]=z4; ap[3]=z4;
}

// ---------------- bilinear helper ------------------------------------------
struct BL { int i00,i10,i01,i11; float w00,w10,w01,w11; };
__device__ __forceinline__ BL mk_bl(float gx, float gy){
    float ix = (gx+1.f)*47.5f;
    float iy = (gy+1.f)*47.5f;
    float fx = floorf(ix), fy = floorf(iy);
    float wx = ix-fx, wy = iy-fy;
    int x0 = max(0,min(95,(int)fx)); int x1 = min(95,x0+1);
    int y0 = max(0,min(95,(int)fy)); int y1 = min(95,y0+1);
    BL r;
    r.i00=(y0*96+x0)*16; r.i10=(y0*96+x1)*16;
    r.i01=(y1*96+x0)*16; r.i11=(y1*96+x1)*16;
    r.w00=(1.f-wx)*(1.f-wy); r.w10=wx*(1.f-wy);
    r.w01=(1.f-wx)*wy;       r.w11=wx*wy;
    return r;
}

// ---------------- fused GRU iteration (R5 proven body) ---------------------
__global__ __launch_bounds__(128) void k_gru(const float* __restrict__ wih, const float* __restrict__ whh,
                                             const float* __restrict__ bih, const float* __restrict__ bhh,
                                             const float* __restrict__ offw, const float* __restrict__ offb,
                                             const float* __restrict__ aw, const float* __restrict__ ab){
    __shared__ float s_wih[48*18], s_whh[48*16], s_bih[48], s_bhh[48];
    __shared__ float s_offw[128], s_offb[8], s_aw[64], s_ab[4];
    int t = threadIdx.x;
    for(int i=t;i<864;i+=128) s_wih[i]=wih[i];
    for(int i=t;i<768;i+=128) s_whh[i]=whh[i];
    if(t<48){ s_bih[t]=bih[t]; s_bhh[t]=bhh[t]; }
    if(t<128) s_offw[t]=offw[t];
    if(t<8)  s_offb[t]=offb[t];
    if(t<64) s_aw[t]=aw[t];
    if(t<4)  s_ab[t]=ab[t];
    __syncthreads();

    int row = blockIdx.x*128 + t;
    int b = row/(NH*HW); int r1 = row%(NH*HW);
    int head = r1/HW; int pix = r1%HW;
    int y = pix/Ww, x = pix%Ww;
    float* offp = g_off + (long)row*8;
    float ox = offp[0], oy = offp[1];
    float gx = clamp1(x*(2.f/95.f)-1.f + ox);
    float gy = clamp1(y*(2.f/95.f)-1.f + oy);

    int nidx = g_near[b];
    const float* vb = g_vt + (((long)(b*Nv+nidx)*NH + head)*HW)*16;
    BL bl = mk_bl(gx, gy);
    float s[16];
    {
        const float4* p00 = (const float4*)(vb + bl.i00);
        const float4* p10 = (const float4*)(vb + bl.i10);
        const float4* p01 = (const float4*)(vb + bl.i01);
        const float4* p11 = (const float4*)(vb + bl.i11);
        #pragma unroll
        for(int g=0; g<4; g++){
            float4 a=p00[g], c=p10[g], d=p01[g], e=p11[g];
            s[g*4+0]=bl.w00*a.x+bl.w10*c.x+bl.w01*d.x+bl.w11*e.x;
            s[g*4+1]=bl.w00*a.y+bl.w10*c.y+bl.w01*d.y+bl.w11*e.y;
            s[g*4+2]=bl.w00*a.z+bl.w10*c.z+bl.w01*d.z+bl.w11*e.z;
            s[g*4+3]=bl.w00*a.w+bl.w10*c.w+bl.w01*d.w+bl.w11*e.w;
        }
    }
    float h_[16];
    {
        float4* np = (float4*)(g_net + (long)row*16);
        #pragma unroll
        for(int g=0; g<4; g++){
            float4 v = np[g];
            h_[g*4+0]=v.x; h_[g*4+1]=v.y; h_[g*4+2]=v.z; h_[g*4+3]=v.w;
        }
    }
    float r[16];
    #pragma unroll
    for(int k=0;k<16;k++){
        float sum = s_bih[k] + s_bhh[k];
        #pragma unroll
        for(int j=0;j<16;j++) sum += s_wih[k*18+j]*s[j];
        sum += s_wih[k*18+16]*ox + s_wih[k*18+17]*oy;
        #pragma unroll
        for(int j=0;j<16;j++) sum += s_whh[k*16+j]*h_[j];
        r[k] = sigmf(sum);
    }
    float nn[16];
    #pragma unroll
    for(int k=0;k<16;k++){
        int kk = 32+k;
        float gin = s_bih[kk];
        #pragma unroll
        for(int j=0;j<16;j++) gin += s_wih[kk*18+j]*s[j];
        gin += s_wih[kk*18+16]*ox + s_wih[kk*18+17]*oy;
        float ghn = s_bhh[kk];
        #pragma unroll
        for(int j=0;j<16;j++) ghn += s_whh[kk*16+j]*h_[j];
        nn[k] = tanhf(gin + r[k]*ghn);
    }
    float nh[16];
    #pragma unroll
    for(int k=0;k<16;k++){
        int kk = 16+k;
        float zs = s_bih[kk] + s_bhh[kk];
        #pragma unroll
        for(int j=0;j<16;j++) zs += s_wih[kk*18+j]*s[j];
        zs += s_wih[kk*18+16]*ox + s_wih[kk*18+17]*oy;
        #pragma unroll
        for(int j=0;j<16;j++) zs += s_whh[kk*16+j]*h_[j];
        float z = sigmf(zs);
        nh[k] = (1.f-z)*nn[k] + z*h_[k];
    }
    {
        float4* np = (float4*)(g_net + (long)row*16);
        #pragma unroll
        for(int g=0; g<4; g++)
            np[g] = make_float4(nh[g*4+0], nh[g*4+1], nh[g*4+2], nh[g*4+3]);
    }
    #pragma unroll
    for(int i=0;i<8;i++){
        float d = s_offb[i];
        #pragma unroll
        for(int k=0;k<16;k++) d += s_offw[i*16+k]*nh[k];
        if(i==0) offp[0] = ox + d;
        else if(i==1) offp[1] = oy + d;
        else offp[i] = offp[i] + d;
    }
    float* ap = g_attn + (long)row*16;
    #pragma unroll
    for(int p=0;p<4;p++){
        float d = s_ab[p];
        #pragma unroll
        for(int k=0;k<16;k++) d += s_aw[p*16+k]*nh[k];
        #pragma unroll
        for(int n=0;n<4;n++) ap[n*4+p] += d;
    }
}

// ---------------- fused softmax + entropy + final sampling -----------------
// Merges R5's k_soft + k_final (both light, no GRU code): saves one launch
// and one full g_attn write+read round trip.
__global__ __launch_bounds__(128) void k_sf(){
    int row = blockIdx.x*128 + threadIdx.x;
    int b = row/(NH*HW); int r1 = row%(NH*HW);
    int head = r1/HW; int pix = r1%HW;
    int y = pix/Ww, x = pix%Ww;

    // softmax over N*P + entropy (from logits in g_attn + time bias)
    float wgt[16];
    {
        const float* ap = g_attn + (long)row*16;
        #pragma unroll
        for(int i=0;i<16;i++) wgt[i] = ap[i];
        #pragma unroll
        for(int n=0;n<4;n++){
            float tb = g_tbias[(b*NH+head)*Nv + n];
            #pragma unroll
            for(int p=0;p<4;p++) wgt[n*4+p] += tb;
        }
        float m = wgt[0];
        #pragma unroll
        for(int i=1;i<16;i++) m = fmaxf(m, wgt[i]);
        float sum = 0.f;
        #pragma unroll
        for(int i=0;i<16;i++){ wgt[i] = expf(wgt[i]-m); sum += wgt[i]; }
        float inv = 1.f/sum;
        float ent = 0.f;
        #pragma unroll
        for(int i=0;i<16;i++){
            wgt[i] *= inv;
            ent -= wgt[i]*logf(wgt[i] + 1e-8f);
        }
        g_entrow[row] = ent;
    }

    // final deformable sampling + aggregation
    float off[8];
    {
        const float* op = g_off + (long)row*8;
        #pragma unroll
        for(int i=0;i<8;i++) off[i] = op[i];
    }
    float bx = x*(2.f/95.f)-1.f, by = y*(2.f/95.f)-1.f;
    float4 acc[4];
    #pragma unroll
    for(int g=0;g<4;g++) acc[g] = make_float4(0.f,0.f,0.f,0.f);

    #pragma unroll
    for(int p=0;p<4;p++){
        float gx = clamp1(bx + off[2*p]);
        float gy = clamp1(by + off[2*p+1]);
        BL bl = mk_bl(gx, gy);
        #pragma unroll
        for(int n=0;n<4;n++){
            float anp = wgt[n*4+p];
            const float* vb2 = g_vt + (((long)(b*Nv+n)*NH + head)*HW)*16;
            float c00 = anp*bl.w00, c10 = anp*bl.w10, c01 = anp*bl.w01, c11 = anp*bl.w11;
            const float4* p00 = (const float4*)(vb2 + bl.i00);
            const float4* p10 = (const float4*)(vb2 + bl.i10);
            const float4* p01 = (const float4*)(vb2 + bl.i01);
            const float4* p11 = (const float4*)(vb2 + bl.i11);
            #pragma unroll
            for(int g=0;g<4;g++){
                float4 v0=p00[g], v1=p10[g], v2=p01[g], v3=p11[g];
                acc[g].x += c00*v0.x + c10*v1.x + c01*v2.x + c11*v3.x;
                acc[g].y += c00*v0.y + c10*v1.y + c01*v2.y + c11*v3.y;
                acc[g].z += c00*v0.z + c10*v1.z + c01*v2.z + c11*v3.z;
                acc[g].w += c00*v0.w + c10*v1.w + c01*v2.w + c11*v3.w;
            }
        }
    }
    float4* og = (float4*)(g_agg + ((long)b*HW + pix)*Cc + head*16);
    #pragma unroll
    for(int g=0;g<4;g++) og[g] = acc[g];
}

// ---------------- entropy mean over heads -> confidence + entropy ----------
__global__ __launch_bounds__(256) void k_ent(float* __restrict__ outp){
    int i = blockIdx.x*256 + threadIdx.x;    // Bq*HW = 18432
    int b = i/HW, pix = i%HW;
    float e = 0.f;
    #pragma unroll
    for(int h=0;h<8;h++) e += g_entrow[(long)(b*NH+h)*HW + pix];
    e *= 0.125f;
    float conf = 1.f - fminf(1.f, fmaxf(0.f, e/(2.77258872f + 1e-8f)));
    outp[(long)Bq*CHW + i]          = conf;
    outp[(long)Bq*CHW + Bq*HW + i]  = e;
}

// ---------------- launch ---------------------------------------------------
extern "C" void kernel_launch(void* const* d_in, const int* in_sizes, int n_in,
                              void* d_out, int out_size){
    const float* query = (const float*)d_in[0];
    const float* values= (const float*)d_in[1];
    const float* rel   = (const float*)d_in[2];
    const float* tenc  = (const float*)d_in[3];
    const float* qw    = (const float*)d_in[4];
    const float* qb    = (const float*)d_in[5];
    const float* vw    = (const float*)d_in[6];
    const float* vb    = (const float*)d_in[7];
    const float* dww   = (const float*)d_in[8];
    const float* dwb   = (const float*)d_in[9];
    const float* pww   = (const float*)d_in[10];
    const float* pwb   = (const float*)d_in[11];
    const float* wih   = (const float*)d_in[12];
    const float* whh   = (const float*)d_in[13];
    const float* bih   = (const float*)d_in[14];
    const float* bhh   = (const float*)d_in[15];
    const float* offw  = (const float*)d_in[16];
    const float* offb  = (const float*)d_in[17];
    const float* aw    = (const float*)d_in[18];
    const float* ab    = (const float*)d_in[19];
    const float* tw    = (const float*)d_in[20];
    const float* tb    = (const float*)d_in[21];
    const float* o1w   = (const float*)d_in[22];
    const float* o1b   = (const float*)d_in[23];
    const float* o2w   = (const float*)d_in[24];
    const float* o2b   = (const float*)d_in[25];
    const float* gate  = (const float*)d_in[26];
    float* outp = (float*)d_out;

    float *p_q, *p_vt, *p_dw, *p_net, *p_agg, *p_tmp;
    cudaGetSymbolAddress((void**)&p_q,   g_q);
    cudaGetSymbolAddress((void**)&p_vt,  g_vt);
    cudaGetSymbolAddress((void**)&p_dw,  g_dw);
    cudaGetSymbolAddress((void**)&p_net, g_net);
    cudaGetSymbolAddress((void**)&p_agg, g_agg);
    cudaGetSymbolAddress((void**)&p_tmp, g_tmp);

    k_prep<<<1,64>>>(rel, tenc, tw, tb);
    k_conv<0,1,0><<<dim3(144,Bq),    256>>>(query,  qw,  qb,  p_q,   nullptr); // q -> net layout
    k_conv<0,1,0><<<dim3(144,Bq*Nv), 256>>>(values, vw,  vb,  p_vt,  nullptr); // v -> net layout
    k_dw  <<<Bq*Cc, 256>>>(query, dww, dwb, p_dw);                              // depthwise + gelu
    k_conv<0,1,0><<<dim3(144,Bq),    256>>>(p_dw,   pww, pwb, p_net, nullptr); // pw -> net (GRU h0)
    k_corr<<<ROWS/256, 256>>>();
    for(int it=0; it<3; it++)
        k_gru<<<ROWS/128, 128>>>(wih, whh, bih, bhh, offw, offb, aw, ab);
    k_sf  <<<ROWS/128, 128>>>();                                                // softmax+entropy+final sample
    k_conv<1,0,1><<<dim3(144,Bq), 256>>>(p_agg, o1w, o1b, p_tmp, nullptr);     // o1 + gelu
    k_conv<0,0,2><<<dim3(144,Bq), 256>>>(p_tmp, o2w, o2b, outp,  gate);        // o2 * sigmoid(gate)
    k_ent<<<Bq*HW/256, 256>>>(outp);
}